// round 14
// baseline (speedup 1.0000x reference)
#include <cuda_runtime.h>
#include <cuda_bf16.h>

#define NN 50000
#define EE 800000
#define BB 256
#define DD 128
#define LL 4

// ---------------- scratch (static device globals; no runtime alloc) ----------
__device__ __align__(16) float    g_H [(size_t)NN * DD];      // fp32 master
__device__ __align__(16) unsigned g_Hb [(size_t)NN * DD / 2]; // bf16x2 packed
__device__ __align__(16) unsigned g_S1b[(size_t)NN * DD / 2];
__device__ __align__(16) unsigned g_S2b[(size_t)NN * DD / 2];
__device__ __align__(16) float    g_T [(size_t)NN * DD];
__device__ __align__(16) float    g_dsq[NN];
__device__            int    g_deg [NN];
__device__            int    g_rowp[NN];
__device__            int    g_cur [NN];
__device__            int    g_btot[256];
__device__ __align__(16) int2  g_epack[EE];   // {src, weight-as-int}
__device__ __align__(16) unsigned g_Wmodb[(size_t)LL * 192 * DD]; // bf16x2, k2-major
__device__ __align__(16) float g_stats[2 * DD];
__device__ __align__(16) float g_pool [BB * DD];
__device__            int    g_cnt  [BB];

#define SCAN_B 196   // ceil(NN/256)

__device__ __forceinline__ void red_add_v4(float* p, float4 v) {
    asm volatile("red.global.add.v4.f32 [%0], {%1,%2,%3,%4};"
                 :: "l"(p), "f"(v.x), "f"(v.y), "f"(v.z), "f"(v.w) : "memory");
}
__device__ __forceinline__ void red_add_f(float* p, float v) {
    asm volatile("red.global.add.f32 [%0], %1;" :: "l"(p), "f"(v) : "memory");
}

__device__ __forceinline__ unsigned packbf(float a, float b) {
    __nv_bfloat162 p = __floats2bfloat162_rn(a, b);
    return *(unsigned*)&p;
}
__device__ __forceinline__ float2 unpackbf(unsigned u) {
    return __bfloat1622float2(*(__nv_bfloat162*)&u);
}

// ---------------- setup ------------------------------------------------------
__global__ void k_init() {
    int i = blockIdx.x * blockDim.x + threadIdx.x;
    if (i < NN) g_deg[i] = 0;
    if (i < BB * DD) g_pool[i] = 0.f;
    if (i < BB) g_cnt[i] = 0;
}

// embed (warp/node) + degree & graph counts + Wmod pack — disjoint jobs
__global__ void k_fused_setup(const int* __restrict__ h_idx,
                              const float* __restrict__ atom_emb,
                              const int* __restrict__ dst,
                              const int* __restrict__ n2g,
                              const float* __restrict__ W) {
    int gid = blockIdx.x * blockDim.x + threadIdx.x;
    int w = gid >> 5;
    if (w < NN) {
        int lane = gid & 31;
        float4 acc = make_float4(0.f, 0.f, 0.f, 0.f);
#pragma unroll
        for (int f = 0; f < 9; f++) {
            int id = __ldg(&h_idx[w * 9 + f]);
            const float4* p = (const float4*)(atom_emb + ((size_t)f * 100 + id) * DD);
            float4 v = p[lane];
            acc.x += v.x; acc.y += v.y; acc.z += v.z; acc.w += v.w;
        }
        int i = w * 32 + lane;
        ((float4*)g_H)[i] = acc;
        ((uint2*)g_Hb)[i] = make_uint2(packbf(acc.x, acc.y), packbf(acc.z, acc.w));
    }
    if (gid < EE) atomicAdd(&g_deg[dst[gid]], 1);
    if (gid < NN) atomicAdd(&g_cnt[n2g[gid]], 1);
    if (gid < LL * 192 * DD) {
        int l = gid / (192 * DD);
        int rem = gid - l * (192 * DD);
        int k2 = rem >> 7;
        int col = rem & 127;
        const float* Wl = W + (size_t)l * 3 * DD * DD;
        float v[2];
#pragma unroll
        for (int q = 0; q < 2; q++) {
            int k = 2 * k2 + q;
            float x = Wl[k * DD + col];
            if (k < DD)            v[q] = x - Wl[(k + 2 * DD) * DD + col];
            else if (k < 2 * DD)   v[q] = -x;
            else                   v[q] = 2.f * x;
        }
        g_Wmodb[gid] = packbf(v[0], v[1]);
    }
}

__global__ void k_scan1() {
    __shared__ int sh[256];
    int t = threadIdx.x;
    int i = blockIdx.x * 256 + t;
    int v = (i < NN) ? g_deg[i] : 0;
    sh[t] = v;
    __syncthreads();
#pragma unroll
    for (int off = 1; off < 256; off <<= 1) {
        int x = (t >= off) ? sh[t - off] : 0;
        __syncthreads();
        sh[t] += x;
        __syncthreads();
    }
    if (i < NN) g_rowp[i] = sh[t] - v;
    if (t == 255) g_btot[blockIdx.x] = sh[255];
}

// each block redundantly scans the block totals, applies its base
__global__ void k_scan23() {
    __shared__ int sh[256];
    int t = threadIdx.x;
    int v = (t < SCAN_B) ? g_btot[t] : 0;
    sh[t] = v;
    __syncthreads();
#pragma unroll
    for (int off = 1; off < 256; off <<= 1) {
        int x = (t >= off) ? sh[t - off] : 0;
        __syncthreads();
        sh[t] += x;
        __syncthreads();
    }
    int base = sh[blockIdx.x] - g_btot[blockIdx.x];
    int i = blockIdx.x * 256 + t;
    if (i >= NN) return;
    int p = g_rowp[i] + base;
    g_rowp[i] = p;
    g_cur[i] = p;
    g_dsq[i] = rsqrtf((float)max(g_deg[i], 1));
}

__global__ void k_place(const int* __restrict__ src, const int* __restrict__ dst) {
    int e = blockIdx.x * blockDim.x + threadIdx.x;
    if (e >= EE) return;
    int d = dst[e], s = src[e];
    int pos = atomicAdd(&g_cur[d], 1);
    g_epack[pos] = make_int2(s, __float_as_int(g_dsq[s] * g_dsq[d]));
}

// ---------------- propagation (bf16 gather, fp32 accumulate) -----------------
// mode 0: g_Hb -> g_S1b ; mode 1: g_S1b -> g_S2b
// mode 1 block 0 also zeroes g_stats (stream-ordered before this layer's GEMM).
__global__ void __launch_bounds__(256) k_prop(int mode) {
    if (mode == 1 && blockIdx.x == 0 && threadIdx.x < 2 * DD)
        g_stats[threadIdx.x] = 0.f;
    int w = (blockIdx.x * blockDim.x + threadIdx.x) >> 5;
    if (w >= NN) return;
    const uint2* x   = (mode == 0) ? (const uint2*)g_Hb  : (const uint2*)g_S1b;
    uint2*       out = (mode == 0) ? (uint2*)g_S1b : (uint2*)g_S2b;
    int lane = threadIdx.x & 31;
    int beg = g_rowp[w];
    int end = beg + g_deg[w];
    float4 acc = make_float4(0.f, 0.f, 0.f, 0.f);
    int e = beg;
    for (; e + 2 <= end; e += 2) {
        int2 p0 = __ldg(&g_epack[e]);
        int2 p1 = __ldg(&g_epack[e + 1]);
        float w0 = __int_as_float(p0.y);
        float w1 = __int_as_float(p1.y);
        uint2 u0 = x[(size_t)p0.x * 32 + lane];
        uint2 u1 = x[(size_t)p1.x * 32 + lane];
        float2 a0 = unpackbf(u0.x), b0 = unpackbf(u0.y);
        float2 a1 = unpackbf(u1.x), b1 = unpackbf(u1.y);
        acc.x += w0 * a0.x + w1 * a1.x;
        acc.y += w0 * a0.y + w1 * a1.y;
        acc.z += w0 * b0.x + w1 * b1.x;
        acc.w += w0 * b0.y + w1 * b1.y;
    }
    if (e < end) {
        int2 p0 = __ldg(&g_epack[e]);
        float w0 = __int_as_float(p0.y);
        uint2 u0 = x[(size_t)p0.x * 32 + lane];
        float2 a0 = unpackbf(u0.x), b0 = unpackbf(u0.y);
        acc.x += w0 * a0.x; acc.y += w0 * a0.y;
        acc.z += w0 * b0.x; acc.w += w0 * b0.y;
    }
    out[(size_t)w * 32 + lane] = make_uint2(packbf(acc.x, acc.y), packbf(acc.z, acc.w));
}

// ------------- bf16 tensor-core GEMM (double-buffered) + fused BN stats ------
#define AST2 20
#define BST2 136
__global__ void __launch_bounds__(256, 2) k_gemm_tc(int layer) {
    const unsigned* Wb = g_Wmodb + (size_t)layer * 192 * DD;
    __shared__ unsigned As[2][128 * AST2];
    __shared__ unsigned Bs[2][16 * BST2];
    __shared__ float ssum[DD], ssq[DD];
    int tid  = threadIdx.x;
    int lane = tid & 31;
    int wid  = tid >> 5;
    int wr = wid & 3;
    int wc = wid >> 2;
    int g  = lane >> 2;
    int t  = lane & 3;
    int row0 = blockIdx.x * 128;

    if (tid < DD) { ssum[tid] = 0.f; ssq[tid] = 0.f; }

    int ar0 = tid >> 2,          ac0 = (tid & 3) * 4;
    int ar1 = (tid + 256) >> 2,  ac1 = ((tid + 256) & 3) * 4;
    int bk0 = tid >> 5,          bc0 = (tid & 31) * 4;
    int bk1 = (tid + 256) >> 5,  bc1 = ((tid + 256) & 31) * 4;

    float c[2][8][4];
#pragma unroll
    for (int i = 0; i < 2; i++)
#pragma unroll
        for (int j = 0; j < 8; j++)
#pragma unroll
            for (int q = 0; q < 4; q++) c[i][j][q] = 0.f;

    uint4 pa0, pa1, pb0, pb1;
    auto fetch = [&](int kt) {
        int k0 = kt * 32;
        const unsigned* srcm = (k0 < DD) ? g_Hb : ((k0 < 2 * DD) ? g_S1b : g_S2b);
        int kin32 = (k0 & (DD - 1)) >> 1;
        pa0 = make_uint4(0u, 0u, 0u, 0u);
        pa1 = make_uint4(0u, 0u, 0u, 0u);
        if (row0 + ar0 < NN)
            pa0 = *(const uint4*)(srcm + (size_t)(row0 + ar0) * 64 + kin32 + ac0);
        if (row0 + ar1 < NN)
            pa1 = *(const uint4*)(srcm + (size_t)(row0 + ar1) * 64 + kin32 + ac1);
        pb0 = *(const uint4*)(Wb + (size_t)(kt * 16 + bk0) * DD + bc0);
        pb1 = *(const uint4*)(Wb + (size_t)(kt * 16 + bk1) * DD + bc1);
    };
    auto commit = [&](int buf) {
        *(uint4*)&As[buf][ar0 * AST2 + ac0] = pa0;
        *(uint4*)&As[buf][ar1 * AST2 + ac1] = pa1;
        *(uint4*)&Bs[buf][bk0 * BST2 + bc0] = pb0;
        *(uint4*)&Bs[buf][bk1 * BST2 + bc1] = pb1;
    };

    fetch(0);
    commit(0);
    __syncthreads();

    for (int kt = 0; kt < 12; kt++) {
        int cur = kt & 1;
        if (kt < 11) fetch(kt + 1);
#pragma unroll
        for (int kk = 0; kk < 2; kk++) {
            int kb2 = kk * 8;
            unsigned a[2][4];
#pragma unroll
            for (int mt = 0; mt < 2; mt++) {
                int rb = wr * 32 + mt * 16;
                a[mt][0] = As[cur][(rb + g)     * AST2 + kb2 + t];
                a[mt][1] = As[cur][(rb + g + 8) * AST2 + kb2 + t];
                a[mt][2] = As[cur][(rb + g)     * AST2 + kb2 + t + 4];
                a[mt][3] = As[cur][(rb + g + 8) * AST2 + kb2 + t + 4];
            }
            unsigned b[8][2];
#pragma unroll
            for (int nt = 0; nt < 8; nt++) {
                int cb = wc * 64 + nt * 8 + g;
                b[nt][0] = Bs[cur][(kb2 + t)     * BST2 + cb];
                b[nt][1] = Bs[cur][(kb2 + t + 4) * BST2 + cb];
            }
#pragma unroll
            for (int mt = 0; mt < 2; mt++)
#pragma unroll
                for (int nt = 0; nt < 8; nt++) {
                    asm volatile(
                        "mma.sync.aligned.m16n8k16.row.col.f32.bf16.bf16.f32 "
                        "{%0,%1,%2,%3}, {%4,%5,%6,%7}, {%8,%9}, {%0,%1,%2,%3};"
                        : "+f"(c[mt][nt][0]), "+f"(c[mt][nt][1]),
                          "+f"(c[mt][nt][2]), "+f"(c[mt][nt][3])
                        : "r"(a[mt][0]), "r"(a[mt][1]), "r"(a[mt][2]), "r"(a[mt][3]),
                          "r"(b[nt][0]), "r"(b[nt][1]));
                }
        }
        if (kt < 11) {
            commit(1 - cur);
            __syncthreads();
        }
    }
    // store T + accumulate per-column stats into smem (OOB rows are exact zeros)
#pragma unroll
    for (int mt = 0; mt < 2; mt++) {
        int r0 = row0 + wr * 32 + mt * 16 + g;
        int r1 = r0 + 8;
#pragma unroll
        for (int nt = 0; nt < 8; nt++) {
            int col = wc * 64 + nt * 8 + t * 2;
            if (r0 < NN)
                *(float2*)(g_T + (size_t)r0 * DD + col) =
                    make_float2(c[mt][nt][0], c[mt][nt][1]);
            if (r1 < NN)
                *(float2*)(g_T + (size_t)r1 * DD + col) =
                    make_float2(c[mt][nt][2], c[mt][nt][3]);
        }
    }
    __syncthreads();   // As/Bs reads done; safe to treat stats as block phase
#pragma unroll
    for (int nt = 0; nt < 8; nt++) {
        int col = wc * 64 + nt * 8 + t * 2;
        float s0 = 0.f, s1 = 0.f, q0 = 0.f, q1 = 0.f;
#pragma unroll
        for (int mt = 0; mt < 2; mt++) {
            float v0 = c[mt][nt][0], v1 = c[mt][nt][1];
            float v2 = c[mt][nt][2], v3 = c[mt][nt][3];
            s0 += v0 + v2; s1 += v1 + v3;
            q0 += v0 * v0 + v2 * v2; q1 += v1 * v1 + v3 * v3;
        }
        atomicAdd(&ssum[col],     s0);
        atomicAdd(&ssum[col + 1], s1);
        atomicAdd(&ssq[col],      q0);
        atomicAdd(&ssq[col + 1],  q1);
    }
    __syncthreads();
    if (tid < DD) {
        red_add_f(&g_stats[tid],      ssum[tid]);
        red_add_f(&g_stats[DD + tid], ssq[tid]);
    }
}

// H += relu( (T - mu) * rstd * gamma + beta ) ; refresh bf16 copy;
// last layer also accumulates mean-pool sums.
__global__ void k_bnres(const float* __restrict__ gamma,
                        const float* __restrict__ beta,
                        int do_pool, const int* __restrict__ n2g) {
    int i = blockIdx.x * blockDim.x + threadIdx.x;
    if (i >= NN * (DD / 4)) return;
    int c4 = (i & 31) * 4;
    const float inv = 1.f / (float)NN;
    float4 s  = *(const float4*)&g_stats[c4];
    float4 s2 = *(const float4*)&g_stats[DD + c4];
    float4 gm = *(const float4*)&gamma[c4];
    float4 bt = *(const float4*)&beta[c4];
    float4 t = ((const float4*)g_T)[i];
    float4 h = ((const float4*)g_H)[i];
#define BN_ONE(X)                                                        \
    {                                                                    \
        float mu = s.X * inv;                                            \
        float var = s2.X * inv - mu * mu;                                \
        float rs = rsqrtf(var + 1e-5f);                                  \
        float v = (t.X - mu) * rs * gm.X + bt.X;                         \
        h.X += fmaxf(v, 0.f);                                            \
    }
    BN_ONE(x) BN_ONE(y) BN_ONE(z) BN_ONE(w)
#undef BN_ONE
    ((float4*)g_H)[i] = h;
    ((uint2*)g_Hb)[i] = make_uint2(packbf(h.x, h.y), packbf(h.z, h.w));
    if (do_pool) {
        int row = i >> 5;
        int gr = __ldg(&n2g[row]);
        red_add_v4(&g_pool[(size_t)gr * DD + c4], h);
    }
}

// ---------------- readout -----------------------------------------------------
__global__ void k_readout(const float* __restrict__ W0, const float* __restrict__ b0,
                          const float* __restrict__ W1, const float* __restrict__ b1,
                          const float* __restrict__ W2, const float* __restrict__ b2,
                          float* __restrict__ out) {
    __shared__ float hg[128], y0[64], y1[32];
    int g = blockIdx.x;
    int t = threadIdx.x;
    float cnt = fmaxf((float)g_cnt[g], 1.f);
    hg[t] = g_pool[g * DD + t] / cnt;
    __syncthreads();
    if (t < 64) {
        float s = b0[t];
#pragma unroll 8
        for (int k = 0; k < 128; k++) s += hg[k] * W0[k * 64 + t];
        y0[t] = fmaxf(s, 0.f);
    }
    __syncthreads();
    if (t < 32) {
        float s = b1[t];
#pragma unroll 8
        for (int k = 0; k < 64; k++) s += y0[k] * W1[k * 32 + t];
        y1[t] = fmaxf(s, 0.f);
    }
    __syncthreads();
    float s = b2[t];
#pragma unroll
    for (int k = 0; k < 32; k++) s += y1[k] * W2[k * 128 + t];
    out[g * 128 + t] = s;
}

// ---------------- driver ------------------------------------------------------
extern "C" void kernel_launch(void* const* d_in, const int* in_sizes, int n_in,
                              void* d_out, int out_size) {
    const int*   h_idx    = (const int*)d_in[0];
    // d_in[1] = e_idx (unused), d_in[6] = bond_emb (unused)
    const int*   src      = (const int*)d_in[2];
    const int*   dst      = (const int*)d_in[3];
    const int*   n2g      = (const int*)d_in[4];
    const float* atom_emb = (const float*)d_in[5];
    const float* layer_W  = (const float*)d_in[7];
    const float* gamma    = (const float*)d_in[8];
    const float* beta     = (const float*)d_in[9];
    const float* W0       = (const float*)d_in[10];
    const float* b0       = (const float*)d_in[11];
    const float* W1       = (const float*)d_in[12];
    const float* b1       = (const float*)d_in[13];
    const float* W2       = (const float*)d_in[14];
    const float* b2       = (const float*)d_in[15];
    float* out = (float*)d_out;

    k_init       <<<(NN + 255) / 256, 256>>>();
    k_fused_setup<<<(NN * 32 + 255) / 256, 256>>>(h_idx, atom_emb, dst, n2g, layer_W);
    k_scan1      <<<SCAN_B, 256>>>();
    k_scan23     <<<SCAN_B, 256>>>();
    k_place      <<<(EE + 255) / 256, 256>>>(src, dst);

    for (int l = 0; l < LL; l++) {
        k_prop<<<(NN * 32 + 255) / 256, 256>>>(0);
        k_prop<<<(NN * 32 + 255) / 256, 256>>>(1);
        k_gemm_tc<<<(NN + 127) / 128, 256>>>(l);
        k_bnres<<<(NN * 32 + 255) / 256, 256>>>(gamma + l * DD, beta + l * DD,
                                                (l == LL - 1) ? 1 : 0, n2g);
    }

    k_readout<<<BB, 128>>>(W0, b0, W1, b1, W2, b2, out);
}

// round 15
// speedup vs baseline: 1.3669x; 1.3669x over previous
#include <cuda_runtime.h>
#include <cuda_bf16.h>

#define NN 50000
#define EE 800000
#define BB 256
#define DD 128
#define LL 4

// ---------------- scratch (static device globals; no runtime alloc) ----------
__device__ __align__(16) float    g_H [(size_t)NN * DD];      // fp32 master
__device__ __align__(16) unsigned g_Hb [(size_t)NN * DD / 2]; // bf16x2 packed
__device__ __align__(16) unsigned g_S1b[(size_t)NN * DD / 2];
__device__ __align__(16) unsigned g_S2b[(size_t)NN * DD / 2];
__device__ __align__(16) float    g_T [(size_t)NN * DD];
__device__ __align__(16) float    g_dsq[NN];
__device__            int    g_deg [NN];
__device__            int    g_rowp[NN];
__device__            int    g_cur [NN];
__device__            int    g_btot[256];
__device__ __align__(16) int2  g_epack[EE];   // {src, weight-as-int}
__device__ __align__(16) unsigned g_Wmodb[(size_t)LL * 192 * DD]; // bf16x2, k2-major
__device__ __align__(16) float g_stats[2 * DD];
__device__ __align__(16) float g_pool [BB * DD];
__device__            int    g_cnt  [BB];

#define SCAN_B 196   // ceil(NN/256)

__device__ __forceinline__ void red_add_v4(float* p, float4 v) {
    asm volatile("red.global.add.v4.f32 [%0], {%1,%2,%3,%4};"
                 :: "l"(p), "f"(v.x), "f"(v.y), "f"(v.z), "f"(v.w) : "memory");
}

__device__ __forceinline__ unsigned packbf(float a, float b) {
    __nv_bfloat162 p = __floats2bfloat162_rn(a, b);
    return *(unsigned*)&p;
}
__device__ __forceinline__ float2 unpackbf(unsigned u) {
    return __bfloat1622float2(*(__nv_bfloat162*)&u);
}

// ---------------- setup ------------------------------------------------------
__global__ void k_init() {
    int i = blockIdx.x * blockDim.x + threadIdx.x;
    if (i < NN) g_deg[i] = 0;
    if (i < BB * DD) g_pool[i] = 0.f;
    if (i < BB) g_cnt[i] = 0;
}

// embed (warp/node) + degree & graph counts + Wmod pack — disjoint jobs
__global__ void k_fused_setup(const int* __restrict__ h_idx,
                              const float* __restrict__ atom_emb,
                              const int* __restrict__ dst,
                              const int* __restrict__ n2g,
                              const float* __restrict__ W) {
    int gid = blockIdx.x * blockDim.x + threadIdx.x;
    int w = gid >> 5;
    if (w < NN) {
        int lane = gid & 31;
        float4 acc = make_float4(0.f, 0.f, 0.f, 0.f);
#pragma unroll
        for (int f = 0; f < 9; f++) {
            int id = __ldg(&h_idx[w * 9 + f]);
            const float4* p = (const float4*)(atom_emb + ((size_t)f * 100 + id) * DD);
            float4 v = p[lane];
            acc.x += v.x; acc.y += v.y; acc.z += v.z; acc.w += v.w;
        }
        int i = w * 32 + lane;
        ((float4*)g_H)[i] = acc;
        ((uint2*)g_Hb)[i] = make_uint2(packbf(acc.x, acc.y), packbf(acc.z, acc.w));
    }
    if (gid < EE) atomicAdd(&g_deg[dst[gid]], 1);
    if (gid < NN) atomicAdd(&g_cnt[n2g[gid]], 1);
    if (gid < LL * 192 * DD) {
        int l = gid / (192 * DD);
        int rem = gid - l * (192 * DD);
        int k2 = rem >> 7;
        int col = rem & 127;
        const float* Wl = W + (size_t)l * 3 * DD * DD;
        float v[2];
#pragma unroll
        for (int q = 0; q < 2; q++) {
            int k = 2 * k2 + q;
            float x = Wl[k * DD + col];
            if (k < DD)            v[q] = x - Wl[(k + 2 * DD) * DD + col];
            else if (k < 2 * DD)   v[q] = -x;
            else                   v[q] = 2.f * x;
        }
        g_Wmodb[gid] = packbf(v[0], v[1]);
    }
}

__global__ void k_scan1() {
    __shared__ int sh[256];
    int t = threadIdx.x;
    int i = blockIdx.x * 256 + t;
    int v = (i < NN) ? g_deg[i] : 0;
    sh[t] = v;
    __syncthreads();
#pragma unroll
    for (int off = 1; off < 256; off <<= 1) {
        int x = (t >= off) ? sh[t - off] : 0;
        __syncthreads();
        sh[t] += x;
        __syncthreads();
    }
    if (i < NN) g_rowp[i] = sh[t] - v;
    if (t == 255) g_btot[blockIdx.x] = sh[255];
}

// each block redundantly scans the block totals, applies its base
__global__ void k_scan23() {
    __shared__ int sh[256];
    int t = threadIdx.x;
    int v = (t < SCAN_B) ? g_btot[t] : 0;
    sh[t] = v;
    __syncthreads();
#pragma unroll
    for (int off = 1; off < 256; off <<= 1) {
        int x = (t >= off) ? sh[t - off] : 0;
        __syncthreads();
        sh[t] += x;
        __syncthreads();
    }
    int base = sh[blockIdx.x] - g_btot[blockIdx.x];
    int i = blockIdx.x * 256 + t;
    if (i >= NN) return;
    int p = g_rowp[i] + base;
    g_rowp[i] = p;
    g_cur[i] = p;
    g_dsq[i] = rsqrtf((float)max(g_deg[i], 1));
}

__global__ void k_place(const int* __restrict__ src, const int* __restrict__ dst) {
    int e = blockIdx.x * blockDim.x + threadIdx.x;
    if (e >= EE) return;
    int d = dst[e], s = src[e];
    int pos = atomicAdd(&g_cur[d], 1);
    g_epack[pos] = make_int2(s, __float_as_int(g_dsq[s] * g_dsq[d]));
}

// ---------------- propagation (bf16 gather, fp32 accumulate) -----------------
// One warp per dst node; half-warp per source row: lanes 0-15 load row s0 as
// uint4, lanes 16-31 load row s1 — one LDG.128 services TWO edges. Lane l and
// l+16 accumulate the same 8 channels; combined by shfl_xor(16) at the end.
// mode 0: g_Hb -> g_S1b ; mode 1: g_S1b -> g_S2b
__global__ void __launch_bounds__(256) k_prop(int mode) {
    int w = (blockIdx.x * blockDim.x + threadIdx.x) >> 5;
    if (w >= NN) return;
    const uint4* x   = (mode == 0) ? (const uint4*)g_Hb  : (const uint4*)g_S1b;
    uint4*       out = (mode == 0) ? (uint4*)g_S1b : (uint4*)g_S2b;
    int lane = threadIdx.x & 31;
    int half = lane >> 4;
    int hl   = lane & 15;
    int beg = g_rowp[w];
    int end = beg + g_deg[w];
    float acc[8];
#pragma unroll
    for (int j = 0; j < 8; j++) acc[j] = 0.f;
    int e = beg;
    for (; e + 2 <= end; e += 2) {
        int2 p0 = __ldg(&g_epack[e]);
        int2 p1 = __ldg(&g_epack[e + 1]);
        int   s  = half ? p1.x : p0.x;
        float wf = __int_as_float(half ? p1.y : p0.y);
        uint4 u = __ldg(&x[(size_t)s * 16 + hl]);
        float2 v0 = unpackbf(u.x), v1 = unpackbf(u.y);
        float2 v2 = unpackbf(u.z), v3 = unpackbf(u.w);
        acc[0] += wf * v0.x; acc[1] += wf * v0.y;
        acc[2] += wf * v1.x; acc[3] += wf * v1.y;
        acc[4] += wf * v2.x; acc[5] += wf * v2.y;
        acc[6] += wf * v3.x; acc[7] += wf * v3.y;
    }
    if (e < end) {                       // odd tail: half 1 contributes zero
        int2 p0 = __ldg(&g_epack[e]);
        float wf = half ? 0.f : __int_as_float(p0.y);
        uint4 u = __ldg(&x[(size_t)p0.x * 16 + hl]);
        float2 v0 = unpackbf(u.x), v1 = unpackbf(u.y);
        float2 v2 = unpackbf(u.z), v3 = unpackbf(u.w);
        acc[0] += wf * v0.x; acc[1] += wf * v0.y;
        acc[2] += wf * v1.x; acc[3] += wf * v1.y;
        acc[4] += wf * v2.x; acc[5] += wf * v2.y;
        acc[6] += wf * v3.x; acc[7] += wf * v3.y;
    }
#pragma unroll
    for (int j = 0; j < 8; j++)
        acc[j] += __shfl_xor_sync(0xffffffffu, acc[j], 16);
    if (half == 0) {
        uint4 r;
        r.x = packbf(acc[0], acc[1]);
        r.y = packbf(acc[2], acc[3]);
        r.z = packbf(acc[4], acc[5]);
        r.w = packbf(acc[6], acc[7]);
        out[(size_t)w * 16 + hl] = r;
    }
}

// ------------- bf16 tensor-core GEMM (double-buffered): T = [H|S1|S2]@Wmod[l]
#define AST2 20
#define BST2 136
__global__ void __launch_bounds__(256, 2) k_gemm_tc(int layer) {
    const unsigned* Wb = g_Wmodb + (size_t)layer * 192 * DD;
    __shared__ unsigned As[2][128 * AST2];
    __shared__ unsigned Bs[2][16 * BST2];
    int tid  = threadIdx.x;
    int lane = tid & 31;
    int wid  = tid >> 5;
    int wr = wid & 3;
    int wc = wid >> 2;
    int g  = lane >> 2;
    int t  = lane & 3;
    int row0 = blockIdx.x * 128;

    if (blockIdx.x == 0 && tid < 2 * DD) g_stats[tid] = 0.f;  // stream-ordered before k_stats

    int ar0 = tid >> 2,          ac0 = (tid & 3) * 4;
    int ar1 = (tid + 256) >> 2,  ac1 = ((tid + 256) & 3) * 4;
    int bk0 = tid >> 5,          bc0 = (tid & 31) * 4;
    int bk1 = (tid + 256) >> 5,  bc1 = ((tid + 256) & 31) * 4;

    float c[2][8][4];
#pragma unroll
    for (int i = 0; i < 2; i++)
#pragma unroll
        for (int j = 0; j < 8; j++)
#pragma unroll
            for (int q = 0; q < 4; q++) c[i][j][q] = 0.f;

    uint4 pa0, pa1, pb0, pb1;
    auto fetch = [&](int kt) {
        int k0 = kt * 32;
        const unsigned* srcm = (k0 < DD) ? g_Hb : ((k0 < 2 * DD) ? g_S1b : g_S2b);
        int kin32 = (k0 & (DD - 1)) >> 1;
        pa0 = make_uint4(0u, 0u, 0u, 0u);
        pa1 = make_uint4(0u, 0u, 0u, 0u);
        if (row0 + ar0 < NN)
            pa0 = *(const uint4*)(srcm + (size_t)(row0 + ar0) * 64 + kin32 + ac0);
        if (row0 + ar1 < NN)
            pa1 = *(const uint4*)(srcm + (size_t)(row0 + ar1) * 64 + kin32 + ac1);
        pb0 = *(const uint4*)(Wb + (size_t)(kt * 16 + bk0) * DD + bc0);
        pb1 = *(const uint4*)(Wb + (size_t)(kt * 16 + bk1) * DD + bc1);
    };
    auto commit = [&](int buf) {
        *(uint4*)&As[buf][ar0 * AST2 + ac0] = pa0;
        *(uint4*)&As[buf][ar1 * AST2 + ac1] = pa1;
        *(uint4*)&Bs[buf][bk0 * BST2 + bc0] = pb0;
        *(uint4*)&Bs[buf][bk1 * BST2 + bc1] = pb1;
    };

    fetch(0);
    commit(0);
    __syncthreads();

    for (int kt = 0; kt < 12; kt++) {
        int cur = kt & 1;
        if (kt < 11) fetch(kt + 1);          // LDGs overlap the MMAs below
#pragma unroll
        for (int kk = 0; kk < 2; kk++) {
            int kb2 = kk * 8;
            unsigned a[2][4];
#pragma unroll
            for (int mt = 0; mt < 2; mt++) {
                int rb = wr * 32 + mt * 16;
                a[mt][0] = As[cur][(rb + g)     * AST2 + kb2 + t];
                a[mt][1] = As[cur][(rb + g + 8) * AST2 + kb2 + t];
                a[mt][2] = As[cur][(rb + g)     * AST2 + kb2 + t + 4];
                a[mt][3] = As[cur][(rb + g + 8) * AST2 + kb2 + t + 4];
            }
            unsigned b[8][2];
#pragma unroll
            for (int nt = 0; nt < 8; nt++) {
                int cb = wc * 64 + nt * 8 + g;
                b[nt][0] = Bs[cur][(kb2 + t)     * BST2 + cb];
                b[nt][1] = Bs[cur][(kb2 + t + 4) * BST2 + cb];
            }
#pragma unroll
            for (int mt = 0; mt < 2; mt++)
#pragma unroll
                for (int nt = 0; nt < 8; nt++) {
                    asm volatile(
                        "mma.sync.aligned.m16n8k16.row.col.f32.bf16.bf16.f32 "
                        "{%0,%1,%2,%3}, {%4,%5,%6,%7}, {%8,%9}, {%0,%1,%2,%3};"
                        : "+f"(c[mt][nt][0]), "+f"(c[mt][nt][1]),
                          "+f"(c[mt][nt][2]), "+f"(c[mt][nt][3])
                        : "r"(a[mt][0]), "r"(a[mt][1]), "r"(a[mt][2]), "r"(a[mt][3]),
                          "r"(b[nt][0]), "r"(b[nt][1]));
                }
        }
        if (kt < 11) {
            commit(1 - cur);
            __syncthreads();
        }
    }
#pragma unroll
    for (int mt = 0; mt < 2; mt++) {
        int r0 = row0 + wr * 32 + mt * 16 + g;
        int r1 = r0 + 8;
#pragma unroll
        for (int nt = 0; nt < 8; nt++) {
            int col = wc * 64 + nt * 8 + t * 2;
            if (r0 < NN)
                *(float2*)(g_T + (size_t)r0 * DD + col) =
                    make_float2(c[mt][nt][0], c[mt][nt][1]);
            if (r1 < NN)
                *(float2*)(g_T + (size_t)r1 * DD + col) =
                    make_float2(c[mt][nt][2], c[mt][nt][3]);
        }
    }
}

// per-channel sum & sumsq over T
__global__ void k_stats() {
    __shared__ float sh1[256], sh2[256];
    int col = threadIdx.x & 127;
    int half = threadIdx.x >> 7;
    int r0 = blockIdx.x * 256;
    int rend = min(r0 + 256, NN);
    float s = 0.f, s2 = 0.f;
    for (int r = r0 + half; r < rend; r += 2) {
        float v = g_T[(size_t)r * DD + col];
        s += v; s2 += v * v;
    }
    sh1[threadIdx.x] = s;
    sh2[threadIdx.x] = s2;
    __syncthreads();
    if (half == 0) {
        atomicAdd(&g_stats[col],      s  + sh1[threadIdx.x + 128]);
        atomicAdd(&g_stats[DD + col], s2 + sh2[threadIdx.x + 128]);
    }
}

// H += relu( (T - mu) * rstd * gamma + beta ) ; refresh bf16 copy;
// last layer also accumulates mean-pool sums.
__global__ void k_bnres(const float* __restrict__ gamma,
                        const float* __restrict__ beta,
                        int do_pool, const int* __restrict__ n2g) {
    int i = blockIdx.x * blockDim.x + threadIdx.x;
    if (i >= NN * (DD / 4)) return;
    int c4 = (i & 31) * 4;
    const float inv = 1.f / (float)NN;
    float4 s  = *(const float4*)&g_stats[c4];
    float4 s2 = *(const float4*)&g_stats[DD + c4];
    float4 gm = *(const float4*)&gamma[c4];
    float4 bt = *(const float4*)&beta[c4];
    float4 t = ((const float4*)g_T)[i];
    float4 h = ((const float4*)g_H)[i];
#define BN_ONE(X)                                                        \
    {                                                                    \
        float mu = s.X * inv;                                            \
        float var = s2.X * inv - mu * mu;                                \
        float rs = rsqrtf(var + 1e-5f);                                  \
        float v = (t.X - mu) * rs * gm.X + bt.X;                         \
        h.X += fmaxf(v, 0.f);                                            \
    }
    BN_ONE(x) BN_ONE(y) BN_ONE(z) BN_ONE(w)
#undef BN_ONE
    ((float4*)g_H)[i] = h;
    ((uint2*)g_Hb)[i] = make_uint2(packbf(h.x, h.y), packbf(h.z, h.w));
    if (do_pool) {
        int row = i >> 5;
        int gr = __ldg(&n2g[row]);
        red_add_v4(&g_pool[(size_t)gr * DD + c4], h);
    }
}

// ---------------- readout -----------------------------------------------------
__global__ void k_readout(const float* __restrict__ W0, const float* __restrict__ b0,
                          const float* __restrict__ W1, const float* __restrict__ b1,
                          const float* __restrict__ W2, const float* __restrict__ b2,
                          float* __restrict__ out) {
    __shared__ float hg[128], y0[64], y1[32];
    int g = blockIdx.x;
    int t = threadIdx.x;
    float cnt = fmaxf((float)g_cnt[g], 1.f);
    hg[t] = g_pool[g * DD + t] / cnt;
    __syncthreads();
    if (t < 64) {
        float s = b0[t];
#pragma unroll 8
        for (int k = 0; k < 128; k++) s += hg[k] * W0[k * 64 + t];
        y0[t] = fmaxf(s, 0.f);
    }
    __syncthreads();
    if (t < 32) {
        float s = b1[t];
#pragma unroll 8
        for (int k = 0; k < 64; k++) s += y0[k] * W1[k * 32 + t];
        y1[t] = fmaxf(s, 0.f);
    }
    __syncthreads();
    float s = b2[t];
#pragma unroll
    for (int k = 0; k < 32; k++) s += y1[k] * W2[k * 128 + t];
    out[g * 128 + t] = s;
}

// ---------------- driver ------------------------------------------------------
extern "C" void kernel_launch(void* const* d_in, const int* in_sizes, int n_in,
                              void* d_out, int out_size) {
    const int*   h_idx    = (const int*)d_in[0];
    // d_in[1] = e_idx (unused), d_in[6] = bond_emb (unused)
    const int*   src      = (const int*)d_in[2];
    const int*   dst      = (const int*)d_in[3];
    const int*   n2g      = (const int*)d_in[4];
    const float* atom_emb = (const float*)d_in[5];
    const float* layer_W  = (const float*)d_in[7];
    const float* gamma    = (const float*)d_in[8];
    const float* beta     = (const float*)d_in[9];
    const float* W0       = (const float*)d_in[10];
    const float* b0       = (const float*)d_in[11];
    const float* W1       = (const float*)d_in[12];
    const float* b1       = (const float*)d_in[13];
    const float* W2       = (const float*)d_in[14];
    const float* b2       = (const float*)d_in[15];
    float* out = (float*)d_out;

    k_init       <<<(NN + 255) / 256, 256>>>();
    k_fused_setup<<<(NN * 32 + 255) / 256, 256>>>(h_idx, atom_emb, dst, n2g, layer_W);
    k_scan1      <<<SCAN_B, 256>>>();
    k_scan23     <<<SCAN_B, 256>>>();
    k_place      <<<(EE + 255) / 256, 256>>>(src, dst);

    for (int l = 0; l < LL; l++) {
        k_prop<<<(NN * 32 + 255) / 256, 256>>>(0);
        k_prop<<<(NN * 32 + 255) / 256, 256>>>(1);
        k_gemm_tc<<<(NN + 127) / 128, 256>>>(l);
        k_stats<<<(NN + 255) / 256, 256>>>();
        k_bnres<<<(NN * 32 + 255) / 256, 256>>>(gamma + l * DD, beta + l * DD,
                                                (l == LL - 1) ? 1 : 0, n2g);
    }

    k_readout<<<BB, 128>>>(W0, b0, W1, b1, W2, b2, out);
}